// round 1
// baseline (speedup 1.0000x reference)
#include <cuda_runtime.h>
#include <math.h>

#define N   2048
#define D   4096
#define NC  8
#define ROWSTRIDE (2 * D)   // features is (N, 2, D); anchor = features[:,0,:]

// ---------------- device scratch (no allocations allowed) ----------------
__device__ float g_s[N];          // per-row  m_i + log Z_i
__device__ int   g_order[N];      // row indices sorted by class
__device__ int   g_cls[N];        // class of sorted position
__device__ int   g_counts[NC];    // class sizes
__device__ float gA[NC * D];      // per-class column sums of p
__device__ float gB[NC * D];      // per-class column sums of logp
__device__ float gE[NC];          // per-class sum of diag (= sum_k p*logp)

// ---------------- K0: histogram + class-sort of rows + zero small ----------------
__global__ void k0_sort(const int* __restrict__ labels) {
    __shared__ int cnt[NC], off[NC];
    int t = threadIdx.x;
    if (t < NC) { cnt[t] = 0; gE[t] = 0.f; }
    __syncthreads();
    for (int i = t; i < N; i += blockDim.x) atomicAdd(&cnt[labels[i]], 1);
    __syncthreads();
    if (t == 0) {
        int run = 0;
        for (int c = 0; c < NC; c++) {
            off[c] = run;
            g_counts[c] = cnt[c];
            run += cnt[c];
        }
    }
    __syncthreads();
    for (int i = t; i < N; i += blockDim.x) {
        int c = labels[i];
        int pos = atomicAdd(&off[c], 1);
        g_order[pos] = i;
        g_cls[pos]   = c;
    }
}

// ---------------- K1: per-row logsumexp stats; blocks <64 also zero gA/gB ----------------
__global__ void k1_stats(const float* __restrict__ feat) {
    const int i = blockIdx.x;   // row
    const int t = threadIdx.x;  // 128 threads

    if (i < 64) {  // zero 2*NC*D = 65536 floats, 1024 per block
        int base = i * 1024;
        for (int j = t; j < 1024; j += 128) {
            int idx = base + j;
            if (idx < NC * D) gA[idx] = 0.f;
            else              gB[idx - NC * D] = 0.f;
        }
    }

    const float* row = feat + (long)i * ROWSTRIDE;
    __shared__ float sred[4];
    __shared__ float sbcast;

    float m = -INFINITY;
    for (int k = t; k < D; k += 128) m = fmaxf(m, row[k]);
    #pragma unroll
    for (int o = 16; o; o >>= 1) m = fmaxf(m, __shfl_xor_sync(0xffffffffu, m, o));
    if ((t & 31) == 0) sred[t >> 5] = m;
    __syncthreads();
    if (t == 0) sbcast = fmaxf(fmaxf(sred[0], sred[1]), fmaxf(sred[2], sred[3]));
    __syncthreads();
    m = sbcast;

    float z = 0.f;
    for (int k = t; k < D; k += 128) z += __expf(row[k] - m);  // row is L1-hot
    #pragma unroll
    for (int o = 16; o; o >>= 1) z += __shfl_xor_sync(0xffffffffu, z, o);
    __syncthreads();            // sred reuse safety
    if ((t & 31) == 0) sred[t >> 5] = z;
    __syncthreads();
    if (t == 0) g_s[i] = m + logf(sred[0] + sred[1] + sred[2] + sred[3]);
}

// ---------------- K2: streaming accumulation of A_c[k], B_c[k], E_c ----------------
// grid (D/128 col-chunks, N/128 row-chunks), 128 threads: thread t owns column k.
__device__ __forceinline__ void flush_seg(int cls, int k, float a, float b, float e, int lane) {
    atomicAdd(&gA[cls * D + k], a);
    atomicAdd(&gB[cls * D + k], b);
    #pragma unroll
    for (int o = 16; o; o >>= 1) e += __shfl_xor_sync(0xffffffffu, e, o);
    if (lane == 0) atomicAdd(&gE[cls], e);
}

__global__ void k2_accum(const float* __restrict__ feat) {
    __shared__ int   srow[128];  // row byte-offset base (in elements)
    __shared__ float ss[128];
    __shared__ int   sc[128];
    const int t = threadIdx.x;
    {
        int idx = blockIdx.y * 128 + t;
        int i = g_order[idx];
        srow[t] = i * ROWSTRIDE;
        ss[t]   = g_s[i];
        sc[t]   = g_cls[idx];
    }
    __syncthreads();

    const int k = blockIdx.x * 128 + t;
    const int lane = t & 31;
    float a = 0.f, b = 0.f, e = 0.f;
    int cur = sc[0];

    #pragma unroll 4
    for (int j = 0; j < 128; j++) {
        int cj = sc[j];
        if (cj != cur) {                 // uniform across block (sorted rows)
            flush_seg(cur, k, a, b, e, lane);
            a = b = e = 0.f;
            cur = cj;
        }
        float x  = __ldg(feat + srow[j] + k);
        float lp = x - ss[j];
        float p  = __expf(lp);
        a += p;
        b += lp;
        e = fmaf(p, lp, e);
    }
    flush_seg(cur, k, a, b, e, lane);
}

// ---------------- K3: dot products + final scalar ----------------
__global__ void k3_final(float* __restrict__ out) {
    __shared__ double red[16][9];
    const int t = threadIdx.x;       // 512 threads = 16 warps
    double scp[NC];
    #pragma unroll
    for (int c = 0; c < NC; c++) scp[c] = 0.0;
    double stot = 0.0;

    for (int k = t; k < D; k += 512) {
        float at = 0.f, bt = 0.f;
        #pragma unroll
        for (int c = 0; c < NC; c++) {
            float av = gA[c * D + k];
            float bv = gB[c * D + k];
            scp[c] += (double)av * (double)bv;
            at += av;
            bt += bv;
        }
        stot += (double)at * (double)bt;
    }

    double vals[9];
    #pragma unroll
    for (int c = 0; c < NC; c++) vals[c] = scp[c];
    vals[8] = stot;
    #pragma unroll
    for (int v = 0; v < 9; v++) {
        double x = vals[v];
        #pragma unroll
        for (int o = 16; o; o >>= 1) x += __shfl_xor_sync(0xffffffffu, x, o);
        if ((t & 31) == 0) red[t >> 5][v] = x;
    }
    __syncthreads();

    if (t == 0) {
        double S[NC], Stot = 0.0;
        for (int c = 0; c < NC; c++) S[c] = 0.0;
        for (int w = 0; w < 16; w++) {
            for (int c = 0; c < NC; c++) S[c] += red[w][c];
            Stot += red[w][8];
        }
        double same = 0.0, diff = 0.0, sumS = 0.0;
        for (int c = 0; c < NC; c++) {
            double E = (double)gE[c];
            double n = (double)g_counts[c];
            same += n * E - S[c];
            diff += ((double)N - n) * E;
            sumS += S[c];
        }
        diff -= (Stot - sumS);
        out[0] = (float)(same / diff);
    }
}

extern "C" void kernel_launch(void* const* d_in, const int* in_sizes, int n_in,
                              void* d_out, int out_size) {
    const float* feat   = (const float*)d_in[0];
    const int*   labels = (const int*)d_in[1];
    float*       out    = (float*)d_out;
    (void)in_sizes; (void)n_in; (void)out_size;

    k0_sort<<<1, 256>>>(labels);
    k1_stats<<<N, 128>>>(feat);
    k2_accum<<<dim3(D / 128, N / 128), 128>>>(feat);
    k3_final<<<1, 512>>>(out);
}

// round 2
// speedup vs baseline: 1.2832x; 1.2832x over previous
#include <cuda_runtime.h>
#include <math.h>

#define N   2048
#define D   4096
#define NC  8
#define ROWSTRIDE (2 * D)   // features is (N, 2, D); anchor = features[:,0,:]

// ---------------- device scratch (no runtime allocations allowed) ----------------
__device__ __align__(16) float g_p[N * D];   // normalized softmax probs (32 MB)
__device__ int    g_order[N];                // row indices sorted by class
__device__ int    g_cls[N];                  // class of sorted position
__device__ int    g_counts[NC];              // class sizes
__device__ float  gA[NC * D];                // per-class column sums of p
__device__ float  gX[NC * D];                // per-class column sums of x
__device__ double g_dot[NC + 1];             // dot(A_c,X_c) per class + dot(At,Xt)
__device__ float  gEsum[NC];                 // per-class sum of row entropy terms
__device__ float  gSsum[NC];                 // per-class sum of s_i = m_i + log Z_i

// ---------------- K0: histogram + class-sort of rows + zero small scratch ----------------
__global__ void k0_sort(const int* __restrict__ labels) {
    __shared__ int cnt[NC], off[NC];
    int t = threadIdx.x;
    if (t < NC) { cnt[t] = 0; gEsum[t] = 0.f; gSsum[t] = 0.f; }
    if (t < NC + 1) g_dot[t] = 0.0;
    __syncthreads();
    for (int i = t; i < N; i += blockDim.x) atomicAdd(&cnt[labels[i]], 1);
    __syncthreads();
    if (t == 0) {
        int run = 0;
        for (int c = 0; c < NC; c++) {
            off[c] = run;
            g_counts[c] = cnt[c];
            run += cnt[c];
        }
    }
    __syncthreads();
    for (int i = t; i < N; i += blockDim.x) {
        int c = labels[i];
        int pos = atomicAdd(&off[c], 1);
        g_order[pos] = i;
        g_cls[pos]   = c;
    }
}

// ---------------- K1: per-row softmax, write p, row-local entropy terms ----------------
// One block per row, 128 threads, row held in registers (32 floats/thread).
__global__ void __launch_bounds__(128) k1_stats(const float* __restrict__ feat,
                                                const int* __restrict__ labels) {
    const int i = blockIdx.x;
    const int t = threadIdx.x;

    // first 64 blocks also zero gA/gX (2*8*4096 floats, 1024 per block)
    if (i < 64) {
        int base = i * 1024;
        #pragma unroll
        for (int j = 0; j < 8; j++) {
            int idx = base + j * 128 + t;
            if (idx < NC * D) gA[idx] = 0.f;
            else              gX[idx - NC * D] = 0.f;
        }
    }

    const float4* row = (const float4*)(feat + (long)i * ROWSTRIDE);
    float4 v[8];
    #pragma unroll
    for (int j = 0; j < 8; j++) v[j] = row[j * 128 + t];

    __shared__ float sred[4], sred2[4];
    __shared__ float sb1, sb2;

    // max
    float m = -INFINITY;
    #pragma unroll
    for (int j = 0; j < 8; j++) {
        m = fmaxf(m, fmaxf(fmaxf(v[j].x, v[j].y), fmaxf(v[j].z, v[j].w)));
    }
    #pragma unroll
    for (int o = 16; o; o >>= 1) m = fmaxf(m, __shfl_xor_sync(0xffffffffu, m, o));
    if ((t & 31) == 0) sred[t >> 5] = m;
    __syncthreads();
    if (t == 0) sb1 = fmaxf(fmaxf(sred[0], sred[1]), fmaxf(sred[2], sred[3]));
    __syncthreads();
    m = sb1;

    // exp (ONLY exp pass in the whole pipeline), Z = sum q, W = sum q*(x-m)
    float z = 0.f, w = 0.f;
    #pragma unroll
    for (int j = 0; j < 8; j++) {
        float tx = v[j].x - m, ty = v[j].y - m, tz = v[j].z - m, tw = v[j].w - m;
        float qx = __expf(tx), qy = __expf(ty), qz = __expf(tz), qw = __expf(tw);
        z += qx + qy + qz + qw;
        w = fmaf(qx, tx, w); w = fmaf(qy, ty, w); w = fmaf(qz, tz, w); w = fmaf(qw, tw, w);
        v[j].x = qx; v[j].y = qy; v[j].z = qz; v[j].w = qw;
    }
    #pragma unroll
    for (int o = 16; o; o >>= 1) {
        z += __shfl_xor_sync(0xffffffffu, z, o);
        w += __shfl_xor_sync(0xffffffffu, w, o);
    }
    __syncthreads();
    if ((t & 31) == 0) { sred[t >> 5] = z; sred2[t >> 5] = w; }
    __syncthreads();
    if (t == 0) {
        sb1 = sred[0] + sred[1] + sred[2] + sred[3];
        sb2 = sred2[0] + sred2[1] + sred2[2] + sred2[3];
    }
    __syncthreads();
    const float Z = sb1, W = sb2;
    const float invZ = 1.0f / Z;
    const float logZ = __logf(Z);

    // write normalized p
    float4* pout = (float4*)(g_p + (long)i * D);
    #pragma unroll
    for (int j = 0; j < 8; j++) {
        float4 q = v[j];
        q.x *= invZ; q.y *= invZ; q.z *= invZ; q.w *= invZ;
        pout[j * 128 + t] = q;
    }

    if (t == 0) {
        int c = labels[i];
        float s = m + logZ;                  // log-sum-exp
        float e_row = W * invZ - logZ;       // sum_k p*logp for this row
        atomicAdd(&gEsum[c], e_row);
        atomicAdd(&gSsum[c], s);
    }
}

// ---------------- K2: exp-free streaming accumulation of A_c[k], X_c[k] ----------------
// grid (D/512, N/128); 128 threads; thread owns 4 consecutive columns (float4).
__device__ __forceinline__ void flush4(int cls, int k0, float4 a, float4 xs) {
    float* pa = &gA[cls * D + k0];
    float* px = &gX[cls * D + k0];
    atomicAdd(pa + 0, a.x); atomicAdd(pa + 1, a.y);
    atomicAdd(pa + 2, a.z); atomicAdd(pa + 3, a.w);
    atomicAdd(px + 0, xs.x); atomicAdd(px + 1, xs.y);
    atomicAdd(px + 2, xs.z); atomicAdd(px + 3, xs.w);
}

__global__ void __launch_bounds__(128) k2_accum(const float* __restrict__ feat) {
    __shared__ int sfr[128];   // feat row base (elements)
    __shared__ int spr[128];   // p row base (elements)
    __shared__ int sc[128];    // class
    const int t = threadIdx.x;
    {
        int idx = blockIdx.y * 128 + t;
        int i = g_order[idx];
        sfr[t] = i * ROWSTRIDE;
        spr[t] = i * D;
        sc[t]  = g_cls[idx];
    }
    __syncthreads();

    const int k0 = blockIdx.x * 512 + t * 4;
    float4 a  = make_float4(0.f, 0.f, 0.f, 0.f);
    float4 xs = make_float4(0.f, 0.f, 0.f, 0.f);
    int cur = sc[0];

    #pragma unroll 4
    for (int j = 0; j < 128; j++) {
        int cj = sc[j];
        if (cj != cur) {                 // uniform across block (rows sorted by class)
            flush4(cur, k0, a, xs);
            a  = make_float4(0.f, 0.f, 0.f, 0.f);
            xs = make_float4(0.f, 0.f, 0.f, 0.f);
            cur = cj;
        }
        float4 x4 = *(const float4*)(feat + sfr[j] + k0);
        float4 p4 = *(const float4*)(g_p + spr[j] + k0);
        a.x += p4.x; a.y += p4.y; a.z += p4.z; a.w += p4.w;
        xs.x += x4.x; xs.y += x4.y; xs.z += x4.z; xs.w += x4.w;
    }
    flush4(cur, k0, a, xs);
}

// ---------------- K3: parallel double-precision dot products ----------------
// 32 blocks x 128 threads; block-reduce 9 doubles, atomicAdd into g_dot.
__global__ void __launch_bounds__(128) k3_dots() {
    const int t = threadIdx.x;
    const int k = blockIdx.x * 128 + t;

    double vals[NC + 1];
    float at = 0.f, xt = 0.f;
    #pragma unroll
    for (int c = 0; c < NC; c++) {
        float av = gA[c * D + k];
        float xv = gX[c * D + k];
        vals[c] = (double)av * (double)xv;
        at += av;
        xt += xv;
    }
    vals[NC] = (double)at * (double)xt;

    __shared__ double red[4][NC + 1];
    #pragma unroll
    for (int vi = 0; vi < NC + 1; vi++) {
        double x = vals[vi];
        #pragma unroll
        for (int o = 16; o; o >>= 1) x += __shfl_xor_sync(0xffffffffu, x, o);
        if ((t & 31) == 0) red[t >> 5][vi] = x;
    }
    __syncthreads();
    if (t < NC + 1) {
        double s = red[0][t] + red[1][t] + red[2][t] + red[3][t];
        atomicAdd(&g_dot[t], s);
    }
}

// ---------------- K4: finalize scalar ----------------
__global__ void k4_final(float* __restrict__ out) {
    if (threadIdx.x != 0) return;
    double same = 0.0, diff = 0.0, sumS = 0.0, Ss_tot = 0.0;
    for (int c = 0; c < NC; c++) {
        double n  = (double)g_counts[c];
        double Sc_s = (double)gSsum[c];
        double E  = (double)gEsum[c];
        double S  = g_dot[c] - Sc_s * n;        // dot(A_c, B_c)
        same += n * E - S;
        diff += ((double)N - n) * E;
        sumS += S;
        Ss_tot += Sc_s;
    }
    double Stot = g_dot[NC] - Ss_tot * (double)N;   // dot(At, Bt)
    diff -= (Stot - sumS);
    out[0] = (float)(same / diff);
}

extern "C" void kernel_launch(void* const* d_in, const int* in_sizes, int n_in,
                              void* d_out, int out_size) {
    const float* feat   = (const float*)d_in[0];
    const int*   labels = (const int*)d_in[1];
    float*       out    = (float*)d_out;
    (void)in_sizes; (void)n_in; (void)out_size;

    k0_sort<<<1, 256>>>(labels);
    k1_stats<<<N, 128>>>(feat, labels);
    k2_accum<<<dim3(D / 512, N / 128), 128>>>(feat);
    k3_dots<<<D / 128, 128>>>();
    k4_final<<<1, 32>>>(out);
}

// round 3
// speedup vs baseline: 2.0882x; 1.6274x over previous
#include <cuda_runtime.h>
#include <math.h>

#define N   2048
#define D   4096
#define NC  8
#define ROWSTRIDE (2 * D)   // features is (N, 2, D); anchor = features[:,0,:]

// ---------------- device scratch (no runtime allocations allowed) ----------------
__device__ int    g_order[N];                 // row indices sorted by class
__device__ int    g_cls[N];                   // class of sorted position
__device__ int    g_counts[NC];               // class sizes
__device__ float  g_s[N];                     // per-row logsumexp s_i = m_i + log Z_i
__device__ __align__(16) float gA[NC * D];    // per-class column sums of p
__device__ __align__(16) float gX[NC * D];    // per-class column sums of x
__device__ double g_dot[NC + 1];              // dot(A_c,X_c) per class + dot(At,Xt)
__device__ float  gEsum[NC];                  // per-class sum of row entropy terms
__device__ float  gSsum[NC];                  // per-class sum of s_i

// ---------------- K0: histogram + class-sort of rows + zero small scratch ----------------
__global__ void k0_sort(const int* __restrict__ labels) {
    __shared__ int cnt[NC], off[NC];
    int t = threadIdx.x;
    if (t < NC) { cnt[t] = 0; gEsum[t] = 0.f; gSsum[t] = 0.f; }
    if (t < NC + 1) g_dot[t] = 0.0;
    __syncthreads();
    for (int i = t; i < N; i += blockDim.x) atomicAdd(&cnt[labels[i]], 1);
    __syncthreads();
    if (t == 0) {
        int run = 0;
        for (int c = 0; c < NC; c++) {
            off[c] = run;
            g_counts[c] = cnt[c];
            run += cnt[c];
        }
    }
    __syncthreads();
    for (int i = t; i < N; i += blockDim.x) {
        int c = labels[i];
        int pos = atomicAdd(&off[c], 1);
        g_order[pos] = i;
        g_cls[pos]   = c;
    }
}

// ---------------- K1: per-row logsumexp + row-local entropy (NO p write) ----------------
// One block per row, 128 threads, row held in registers (32 floats/thread).
__global__ void __launch_bounds__(128) k1_stats(const float* __restrict__ feat,
                                                const int* __restrict__ labels) {
    const int i = blockIdx.x;
    const int t = threadIdx.x;

    // first 64 blocks also zero gA/gX (2*8*4096 floats, 1024 per block)
    if (i < 64) {
        int base = i * 1024;
        #pragma unroll
        for (int j = 0; j < 8; j++) {
            int idx = base + j * 128 + t;
            if (idx < NC * D) gA[idx] = 0.f;
            else              gX[idx - NC * D] = 0.f;
        }
    }

    const float4* row = (const float4*)(feat + (long)i * ROWSTRIDE);
    float4 v[8];
    #pragma unroll
    for (int j = 0; j < 8; j++) v[j] = row[j * 128 + t];

    __shared__ float sred[4], sred2[4];
    __shared__ float sb1, sb2;

    // max
    float m = -INFINITY;
    #pragma unroll
    for (int j = 0; j < 8; j++)
        m = fmaxf(m, fmaxf(fmaxf(v[j].x, v[j].y), fmaxf(v[j].z, v[j].w)));
    #pragma unroll
    for (int o = 16; o; o >>= 1) m = fmaxf(m, __shfl_xor_sync(0xffffffffu, m, o));
    if ((t & 31) == 0) sred[t >> 5] = m;
    __syncthreads();
    if (t == 0) sb1 = fmaxf(fmaxf(sred[0], sred[1]), fmaxf(sred[2], sred[3]));
    __syncthreads();
    m = sb1;

    // Z = sum exp(x-m), W = sum exp(x-m)*(x-m)
    float z = 0.f, w = 0.f;
    #pragma unroll
    for (int j = 0; j < 8; j++) {
        float tx = v[j].x - m, ty = v[j].y - m, tz = v[j].z - m, tw = v[j].w - m;
        float qx = __expf(tx), qy = __expf(ty), qz = __expf(tz), qw = __expf(tw);
        z += qx + qy + qz + qw;
        w = fmaf(qx, tx, w); w = fmaf(qy, ty, w); w = fmaf(qz, tz, w); w = fmaf(qw, tw, w);
    }
    #pragma unroll
    for (int o = 16; o; o >>= 1) {
        z += __shfl_xor_sync(0xffffffffu, z, o);
        w += __shfl_xor_sync(0xffffffffu, w, o);
    }
    if ((t & 31) == 0) { sred[t >> 5] = z; sred2[t >> 5] = w; }
    __syncthreads();
    if (t == 0) {
        float Z = sred[0] + sred[1] + sred[2] + sred[3];
        float W = sred2[0] + sred2[1] + sred2[2] + sred2[3];
        float logZ = __logf(Z);
        float s = m + logZ;
        g_s[i] = s;
        int c = labels[i];
        atomicAdd(&gEsum[c], W / Z - logZ);   // sum_k p*logp for this row
        atomicAdd(&gSsum[c], s);
    }
}

// ---------------- K2: streaming accumulation of A_c[k], X_c[k] (recompute exp) ----------------
// grid (D/512, N/64); 128 threads; thread owns 4 consecutive columns.
__device__ __forceinline__ void flush4(int cls, int k0, float4 a, float4 xs) {
    float* pa = &gA[cls * D + k0];
    float* px = &gX[cls * D + k0];
    atomicAdd(pa + 0, a.x); atomicAdd(pa + 1, a.y);
    atomicAdd(pa + 2, a.z); atomicAdd(pa + 3, a.w);
    atomicAdd(px + 0, xs.x); atomicAdd(px + 1, xs.y);
    atomicAdd(px + 2, xs.z); atomicAdd(px + 3, xs.w);
}

#define RPB 64   // rows per block

__global__ void __launch_bounds__(128) k2_accum(const float* __restrict__ feat) {
    __shared__ int   sfr[RPB];   // feat row base (elements)
    __shared__ float ss[RPB];    // s_i for row
    __shared__ int   sc[RPB];    // class
    const int t = threadIdx.x;
    if (t < RPB) {
        int idx = blockIdx.y * RPB + t;
        int i = g_order[idx];
        sfr[t] = i * ROWSTRIDE;
        ss[t]  = g_s[i];
        sc[t]  = g_cls[idx];
    }
    __syncthreads();

    const int k0 = blockIdx.x * 512 + t * 4;
    float4 a  = make_float4(0.f, 0.f, 0.f, 0.f);
    float4 xs = make_float4(0.f, 0.f, 0.f, 0.f);
    int cur = sc[0];

    #pragma unroll 4
    for (int j = 0; j < RPB; j++) {
        int cj = sc[j];
        if (cj != cur) {                 // uniform across block (rows sorted by class)
            flush4(cur, k0, a, xs);
            a  = make_float4(0.f, 0.f, 0.f, 0.f);
            xs = make_float4(0.f, 0.f, 0.f, 0.f);
            cur = cj;
        }
        float4 x4 = *(const float4*)(feat + sfr[j] + k0);
        float sj = ss[j];
        a.x += __expf(x4.x - sj); a.y += __expf(x4.y - sj);
        a.z += __expf(x4.z - sj); a.w += __expf(x4.w - sj);
        xs.x += x4.x; xs.y += x4.y; xs.z += x4.z; xs.w += x4.w;
    }
    flush4(cur, k0, a, xs);
}

// ---------------- K3: double-precision dots, one value per block ----------------
// grid (4, NC+1): block (x, c) computes partial dot for value c over 1024 columns.
__global__ void __launch_bounds__(256) k3_dots() {
    const int t = threadIdx.x;
    const int c = blockIdx.y;
    const int k0 = blockIdx.x * 1024 + t * 4;

    double part = 0.0;
    if (c < NC) {
        float4 a = *(const float4*)&gA[c * D + k0];
        float4 x = *(const float4*)&gX[c * D + k0];
        part = (double)a.x * (double)x.x + (double)a.y * (double)x.y
             + (double)a.z * (double)x.z + (double)a.w * (double)x.w;
    } else {
        float at[4] = {0.f, 0.f, 0.f, 0.f};
        float xt[4] = {0.f, 0.f, 0.f, 0.f};
        #pragma unroll
        for (int cc = 0; cc < NC; cc++) {
            float4 a = *(const float4*)&gA[cc * D + k0];
            float4 x = *(const float4*)&gX[cc * D + k0];
            at[0] += a.x; at[1] += a.y; at[2] += a.z; at[3] += a.w;
            xt[0] += x.x; xt[1] += x.y; xt[2] += x.z; xt[3] += x.w;
        }
        #pragma unroll
        for (int q = 0; q < 4; q++) part += (double)at[q] * (double)xt[q];
    }

    #pragma unroll
    for (int o = 16; o; o >>= 1) part += __shfl_xor_sync(0xffffffffu, part, o);
    __shared__ double red[8];
    if ((t & 31) == 0) red[t >> 5] = part;
    __syncthreads();
    if (t == 0) {
        double s = 0.0;
        #pragma unroll
        for (int w = 0; w < 8; w++) s += red[w];
        atomicAdd(&g_dot[c], s);
    }
}

// ---------------- K4: finalize scalar ----------------
__global__ void k4_final(float* __restrict__ out) {
    if (threadIdx.x != 0) return;
    double same = 0.0, diff = 0.0, sumS = 0.0, Ss_tot = 0.0;
    for (int c = 0; c < NC; c++) {
        double n    = (double)g_counts[c];
        double Sc_s = (double)gSsum[c];
        double E    = (double)gEsum[c];
        double S    = g_dot[c] - Sc_s * n;        // dot(A_c, B_c)
        same += n * E - S;
        diff += ((double)N - n) * E;
        sumS += S;
        Ss_tot += Sc_s;
    }
    double Stot = g_dot[NC] - Ss_tot * (double)N; // dot(At, Bt)
    diff -= (Stot - sumS);
    out[0] = (float)(same / diff);
}

extern "C" void kernel_launch(void* const* d_in, const int* in_sizes, int n_in,
                              void* d_out, int out_size) {
    const float* feat   = (const float*)d_in[0];
    const int*   labels = (const int*)d_in[1];
    float*       out    = (float*)d_out;
    (void)in_sizes; (void)n_in; (void)out_size;

    k0_sort<<<1, 256>>>(labels);
    k1_stats<<<N, 128>>>(feat, labels);
    k2_accum<<<dim3(D / 512, N / RPB), 128>>>(feat);
    k3_dots<<<dim3(4, NC + 1), 256>>>();
    k4_final<<<1, 32>>>(out);
}